// round 6
// baseline (speedup 1.0000x reference)
#include <cuda_runtime.h>
#include <cuda_bf16.h>
#include <cuda_fp8.h>
#include <cstdint>

#define B_Q   256
#define N_MEM 50000
#define D_DIM 1024
#define NTILE 128
#define KC    128                            // fp8 elements per chunk (128B row)
#define NCHUNK (D_DIM / KC)                  // 8
#define NBLK  ((N_MEM + NTILE - 1) / NTILE)  // 391

// SMEM (dynamic): double-buffered Q (256x128B) and M (128x128B)
#define SM_Q     0                       // 2 x 32KB
#define SM_M     65536                   // 2 x 16KB
#define SM_NORM  (SM_M + 32768)          // 128 floats
#define SMEM_TOTAL (SM_NORM + 512)

__device__ unsigned long long g_best[B_Q];
__device__ int g_sel[B_Q];
__device__ uint8_t g_q8[B_Q * D_DIM];

__device__ __forceinline__ uint32_t smem_u32(const void* p) {
    uint32_t a;
    asm("{ .reg .u64 t; cvta.to.shared.u64 t, %1; cvt.u32.u64 %0, t; }" : "=r"(a) : "l"(p));
    return a;
}
__device__ __forceinline__ unsigned int fkey(float f) {
    unsigned int u = __float_as_uint(f);
    return (u & 0x80000000u) ? ~u : (u | 0x80000000u);
}
#define SW128(off) ((off) ^ (((off) >> 3) & 0x70))

#define LDSM_X4(r0, r1, r2, r3, a) \
    asm volatile("ldmatrix.sync.aligned.m8n8.x4.shared.b16 {%0,%1,%2,%3}, [%4];" \
                 : "=r"(r0), "=r"(r1), "=r"(r2), "=r"(r3) : "r"(a))
#define MMA_FP8(d, a, b0, b1) \
    asm volatile("mma.sync.aligned.m16n8k32.row.col.f32.e4m3.e4m3.f32 " \
                 "{%0,%1,%2,%3}, {%4,%5,%6,%7}, {%8,%9}, {%0,%1,%2,%3};" \
                 : "+f"((d)[0]), "+f"((d)[1]), "+f"((d)[2]), "+f"((d)[3]) \
                 : "r"((a)[0]), "r"((a)[1]), "r"((a)[2]), "r"((a)[3]), "r"(b0), "r"(b1))
#define CP_ASYNC_16(dst, src) \
    asm volatile("cp.async.cg.shared.global [%0], [%1], 16;" :: "r"(dst), "l"(src) : "memory")
#define CP_ASYNC_COMMIT() asm volatile("cp.async.commit_group;" ::: "memory")
#define CP_ASYNC_WAIT(n)  asm volatile("cp.async.wait_group %0;" :: "n"(n) : "memory")

__device__ __forceinline__ uint32_t pack_fp8x4(float x, float y, float z, float w) {
    __nv_fp8x2_storage_t lo = __nv_cvt_float2_to_fp8x2(make_float2(x, y), __NV_SATFINITE, __NV_E4M3);
    __nv_fp8x2_storage_t hi = __nv_cvt_float2_to_fp8x2(make_float2(z, w), __NV_SATFINITE, __NV_E4M3);
    return (uint32_t)lo | ((uint32_t)hi << 16);
}

// Q fp32 -> e4m3 once; reset g_best.
__global__ __launch_bounds__(256) void prep_kernel(const float* __restrict__ Q) {
    int idx = blockIdx.x * 256 + threadIdx.x;            // one float4 -> 4 fp8
    const float4 v = reinterpret_cast<const float4*>(Q)[idx];
    reinterpret_cast<uint32_t*>(g_q8)[idx] = pack_fp8x4(v.x, v.y, v.z, v.w);
    if (blockIdx.x == 0) g_best[threadIdx.x] = 0ull;
}

// FP8 tensor-core GEMM (256q x 128n x 1024k) + fused row norms + argmax merge.
// 512 threads, 16 warps (4 wq x 4 wn), warp tile 64q x 32n, double-buffered smem.
__global__ __launch_bounds__(512, 1) void simmax_mma(const float* __restrict__ Mptr) {
    extern __shared__ char smem[];
    const uint32_t sb = smem_u32(smem);
    const int tid = threadIdx.x;
    const int l   = tid & 31;
    const int wid = tid >> 5;
    const int wq  = wid >> 2;
    const int wn  = wid & 3;
    const int ntile = blockIdx.x * NTILE;

    float* norms = reinterpret_cast<float*>(smem + SM_NORM);
    if (tid < NTILE) norms[tid] = 0.0f;
    __syncthreads();

    float acc[4][4][4];
#pragma unroll
    for (int mt = 0; mt < 4; mt++)
#pragma unroll
        for (int nt = 0; nt < 4; nt++)
#pragma unroll
            for (int v = 0; v < 4; v++) acc[mt][nt][v] = 0.0f;

    // M loader: 4 threads per row; thread covers 32 floats (8 float4)
    const int mrow = tid >> 2;
    const int mq4  = tid & 3;
    const int gn   = ntile + mrow;
    const bool mvalid = (gn < N_MEM);
    const float* msrc = Mptr + (size_t)gn * D_DIM + mq4 * 32;
    float4 f[8];
    float sumsq = 0.0f;

    // Q loader: 2048 16B segs per chunk, 4 per thread
    auto issue_q = [&](int c, int slot) {
        const uint32_t qbase = sb + SM_Q + slot * 32768;
#pragma unroll
        for (int i = 0; i < 4; i++) {
            int s = tid + 512 * i;
            int qrow = s >> 3, qseg = s & 7;
            const void* src = g_q8 + (size_t)qrow * D_DIM + c * KC + qseg * 16;
            uint32_t off = (uint32_t)(qrow * 128 + qseg * 16);
            CP_ASYNC_16(qbase + SW128(off), src);
        }
        CP_ASYNC_COMMIT();
    };

    // ---- prologue: Q(0) async, M(0) regs
    issue_q(0, 0);
#pragma unroll
    for (int i = 0; i < 8; i++)
        f[i] = mvalid ? *reinterpret_cast<const float4*>(msrc + i * 4)
                      : make_float4(0.f, 0.f, 0.f, 0.f);

    const int lrow = l & 15;
    const int lhi  = (l >> 4) * 16;

    for (int c = 0; c < NCHUNK; c++) {
        const int slot = c & 1;
        // ---- STS M(c): convert fp32->e4m3, fused sumsq
        {
            uint32_t w[8];
#pragma unroll
            for (int i = 0; i < 8; i++) {
                sumsq += f[i].x * f[i].x + f[i].y * f[i].y + f[i].z * f[i].z + f[i].w * f[i].w;
                w[i] = pack_fp8x4(f[i].x, f[i].y, f[i].z, f[i].w);
            }
            uint32_t off = (uint32_t)(mrow * 128 + mq4 * 32);
            *reinterpret_cast<uint4*>(smem + SM_M + slot * 16384 + SW128(off))      = *reinterpret_cast<uint4*>(&w[0]);
            *reinterpret_cast<uint4*>(smem + SM_M + slot * 16384 + SW128(off + 16)) = *reinterpret_cast<uint4*>(&w[4]);
        }
        // ---- prefetch next chunk (overlaps compute below)
        if (c + 1 < NCHUNK) {
            issue_q(c + 1, slot ^ 1);
#pragma unroll
            for (int i = 0; i < 8; i++)
                f[i] = mvalid ? *reinterpret_cast<const float4*>(msrc + (c + 1) * KC + i * 4)
                              : make_float4(0.f, 0.f, 0.f, 0.f);
            CP_ASYNC_WAIT(1);   // Q(c) landed, Q(c+1) may fly
        } else {
            CP_ASYNC_WAIT(0);
        }
        __syncthreads();

        // ---- compute chunk c: 4 k32 steps
        const uint32_t qbase = sb + SM_Q + slot * 32768;
        const uint32_t mbase = sb + SM_M + slot * 16384;
#pragma unroll
        for (int ks = 0; ks < 4; ks++) {
            uint32_t b[4];   // 2 n8-tiles x (k0-15, k16-31) for 16 n rows; x4 covers 16n
            {
                uint32_t off = (uint32_t)((wn * 32 + lrow) * 128 + ks * 32 + lhi);
                LDSM_X4(b[0], b[1], b[2], b[3], mbase + SW128(off));
            }
            uint32_t b2[4];
            {
                uint32_t off = (uint32_t)((wn * 32 + 16 + lrow) * 128 + ks * 32 + lhi);
                LDSM_X4(b2[0], b2[1], b2[2], b2[3], mbase + SW128(off));
            }
#pragma unroll
            for (int mt = 0; mt < 4; mt++) {
                uint32_t a[4];
                uint32_t off = (uint32_t)((wq * 64 + mt * 16 + lrow) * 128 + ks * 32 + lhi);
                LDSM_X4(a[0], a[1], a[2], a[3], qbase + SW128(off));
                MMA_FP8(acc[mt][0], a, b[0],  b[2]);
                MMA_FP8(acc[mt][1], a, b[1],  b[3]);
                MMA_FP8(acc[mt][2], a, b2[0], b2[2]);
                MMA_FP8(acc[mt][3], a, b2[1], b2[3]);
            }
        }
        __syncthreads();
    }

    // ---- row norms (4 threads/row, fp32 exact)
    sumsq += __shfl_xor_sync(0xFFFFFFFFu, sumsq, 1);
    sumsq += __shfl_xor_sync(0xFFFFFFFFu, sumsq, 2);
    if (mq4 == 0) norms[mrow] = rsqrtf(fmaxf(sumsq, 1e-30f));
    __syncthreads();
    const float* invn = norms;

    // ---- epilogue: per-q-row argmax over this CTA's 128 n
#pragma unroll
    for (int mt = 0; mt < 4; mt++) {
#pragma unroll
        for (int sub = 0; sub < 2; sub++) {
            unsigned long long best = 0ull;
#pragma unroll
            for (int nt = 0; nt < 4; nt++) {
#pragma unroll
                for (int cc = 0; cc < 2; cc++) {
                    int nl = wn * 32 + nt * 8 + 2 * (l & 3) + cc;
                    int n = ntile + nl;
                    if (n < N_MEM) {
                        float s = acc[mt][nt][sub * 2 + cc] * invn[nl];
                        unsigned long long key =
                            ((unsigned long long)fkey(s) << 32) |
                            (unsigned long long)(unsigned int)(~(unsigned int)n);
                        if (key > best) best = key;
                    }
                }
            }
            unsigned long long o;
            o = __shfl_xor_sync(0xFFFFFFFFu, best, 1); if (o > best) best = o;
            o = __shfl_xor_sync(0xFFFFFFFFu, best, 2); if (o > best) best = o;
            if ((l & 3) == 0) {
                int q = wq * 64 + mt * 16 + (l >> 2) + sub * 8;
                atomicMax(&g_best[q], best);
            }
        }
    }
}

// Exact fp32 recompute of the winner's cosine sim + threshold.
__global__ __launch_bounds__(256) void finalize_kernel(const float* __restrict__ Q,
                                                       const float* __restrict__ M) {
    __shared__ float sdq[256], sdm[256], sdp[256];
    const int b = blockIdx.x;
    const int tid = threadIdx.x;

    unsigned long long pk = g_best[b];
    int idx = (int)(~(unsigned int)(pk & 0xFFFFFFFFull));

    const float* q = Q + (size_t)b * D_DIM;
    const float* m = M + (size_t)idx * D_DIM;
    float dq = 0.f, dm = 0.f, dp = 0.f;
    for (int k = tid * 4; k < D_DIM; k += 256 * 4) {
        float4 qa = *reinterpret_cast<const float4*>(&q[k]);
        float4 mb = *reinterpret_cast<const float4*>(&m[k]);
        dq += qa.x * qa.x + qa.y * qa.y + qa.z * qa.z + qa.w * qa.w;
        dm += mb.x * mb.x + mb.y * mb.y + mb.z * mb.z + mb.w * mb.w;
        dp += qa.x * mb.x + qa.y * mb.y + qa.z * mb.z + qa.w * mb.w;
    }
    sdq[tid] = dq; sdm[tid] = dm; sdp[tid] = dp;
    __syncthreads();
    for (int s = 128; s > 0; s >>= 1) {
        if (tid < s) {
            sdq[tid] += sdq[tid + s];
            sdm[tid] += sdm[tid + s];
            sdp[tid] += sdp[tid + s];
        }
        __syncthreads();
    }
    if (tid == 0) {
        float sim = sdp[0] / fmaxf(sqrtf(sdq[0]) * sqrtf(sdm[0]), 1e-8f);
        g_sel[b] = (sim > 0.6f) ? idx : -1;
    }
}

__global__ __launch_bounds__(128) void decode_kernel(const float* __restrict__ M,
                                                     const float* __restrict__ W,
                                                     const float* __restrict__ bias,
                                                     float* __restrict__ out) {
    const int b = blockIdx.y;
    const int j = blockIdx.x * 128 + threadIdx.x;
    const int sel = g_sel[b];
    float r = 0.0f;
    if (sel >= 0) {
        const float* e = M + (size_t)sel * D_DIM;
        const float* w = W + (size_t)j * D_DIM;
        float s = 0.0f;
        for (int k = 0; k < D_DIM; k += 4) {
            float4 ev = *reinterpret_cast<const float4*>(&e[k]);
            float4 wv = *reinterpret_cast<const float4*>(&w[k]);
            s += ev.x * wv.x + ev.y * wv.y + ev.z * wv.z + ev.w * wv.w;
        }
        r = s + bias[j];
    }
    out[(size_t)b * D_DIM + j] = r;
}

extern "C" void kernel_launch(void* const* d_in, const int* in_sizes, int n_in,
                              void* d_out, int out_size) {
    const float* Q    = (const float*)d_in[0];
    const float* M    = (const float*)d_in[1];
    const float* W    = (const float*)d_in[2];
    const float* bias = (const float*)d_in[3];
    float* out = (float*)d_out;

    cudaFuncSetAttribute(simmax_mma, cudaFuncAttributeMaxDynamicSharedMemorySize, SMEM_TOTAL);

    prep_kernel<<<B_Q * D_DIM / 4 / 256, 256>>>(Q);
    simmax_mma<<<NBLK, 512, SMEM_TOTAL>>>(M);
    finalize_kernel<<<B_Q, 256>>>(Q, M);
    decode_kernel<<<dim3(D_DIM / 128, B_Q), 128>>>(M, W, bias, out);
}